// round 12
// baseline (speedup 1.0000x reference)
#include <cuda_runtime.h>

// Screen geometry (must match reference exactly, as float32)
#define NX 1024
#define NY 1024
// LEFT = -RES_X*PIX_X/2 = -0.00512 ; HSTEP = 1e-5 (binning=1)
__device__ __constant__ float c_LEFT   = -0.00512f;
__device__ __constant__ float c_RIGHT  =  0.00512f;
__device__ __constant__ float c_BOTTOM = -0.00512f;
__device__ __constant__ float c_TOP    =  0.00512f;
__device__ __constant__ float c_HSTEP  =  1e-5f;
__device__ __constant__ float c_VSTEP  =  1e-5f;

#define N_PARTICLES 16777216
#define TPB 512     // block-size sweep: halves CTAs/SM -> less cross-CTA L1tex queue skew

__global__ void zero_out_kernel(float4* __restrict__ out, int n4) {
    int i = blockIdx.x * blockDim.x + threadIdx.x;
    if (i < n4) out[i] = make_float4(0.f, 0.f, 0.f, 0.f);
}

__device__ __forceinline__ void deposit(float x, float y, float* __restrict__ out) {
    // Match jnp.floor((x - LEFT)/HSTEP) in fp32 with IEEE round-to-nearest division.
    bool valid = (x >= c_LEFT) & (x <= c_RIGHT) & (y >= c_BOTTOM) & (y <= c_TOP);
    if (!valid) return;
    int ix = (int)floorf(__fdiv_rn(x - c_LEFT,   c_HSTEP));
    int iy = (int)floorf(__fdiv_rn(y - c_BOTTOM, c_VSTEP));
    if (x == c_RIGHT) ix = NX - 1;
    if (y == c_TOP)   iy = NY - 1;
    ix = min(max(ix, 0), NX - 1);
    iy = min(max(iy, 0), NY - 1);
    int flat = (NY - 1 - iy) * NX + ix;
    atomicAdd(out + flat, 1.0f);  // no return use -> RED.E.ADD.F32
}

__global__ void __launch_bounds__(TPB)
hist_kernel(const float4* __restrict__ xs4, const float4* __restrict__ ys4,
            const float* __restrict__ mis, float* __restrict__ out) {
    int i = blockIdx.x * blockDim.x + threadIdx.x;  // one float4 per thread
    float mx = mis[0];
    float my = mis[1];
    float4 x4 = xs4[i];
    float4 y4 = ys4[i];
    deposit(x4.x - mx, y4.x - my, out);
    deposit(x4.y - mx, y4.y - my, out);
    deposit(x4.z - mx, y4.z - my, out);
    deposit(x4.w - mx, y4.w - my, out);
}

extern "C" void kernel_launch(void* const* d_in, const int* in_sizes, int n_in,
                              void* d_out, int out_size) {
    const float* xs  = (const float*)d_in[0];
    const float* ys  = (const float*)d_in[1];
    const float* mis = (const float*)d_in[2];
    float* out = (float*)d_out;

    // 1) zero the image (out_size = NX*NY floats, divisible by 4)
    int n4 = out_size / 4;
    zero_out_kernel<<<(n4 + 255) / 256, 256>>>((float4*)out, n4);

    // 2) histogram: 16,777,216 particles, 4 per thread, 512-thread blocks
    int work = N_PARTICLES / 4;          // 4,194,304 threads
    hist_kernel<<<work / TPB, TPB>>>((const float4*)xs, (const float4*)ys, mis, out);
}

// round 13
// speedup vs baseline: 1.0023x; 1.0023x over previous
#include <cuda_runtime.h>

// Screen geometry (must match reference exactly, as float32)
#define NX 1024
#define NY 1024
// LEFT = -RES_X*PIX_X/2 = -0.00512 ; HSTEP = 1e-5 (binning=1)
__device__ __constant__ float c_LEFT   = -0.00512f;
__device__ __constant__ float c_RIGHT  =  0.00512f;
__device__ __constant__ float c_BOTTOM = -0.00512f;
__device__ __constant__ float c_TOP    =  0.00512f;
__device__ __constant__ float c_HSTEP  =  1e-5f;
__device__ __constant__ float c_VSTEP  =  1e-5f;

#define N_PARTICLES 16777216

__global__ void zero_out_kernel(float4* __restrict__ out, int n4) {
    int i = blockIdx.x * blockDim.x + threadIdx.x;
    if (i < n4) out[i] = make_float4(0.f, 0.f, 0.f, 0.f);
}

__device__ __forceinline__ void deposit(float x, float y, float* __restrict__ out) {
    // Match jnp.floor((x - LEFT)/HSTEP) in fp32 with IEEE round-to-nearest division.
    bool valid = (x >= c_LEFT) & (x <= c_RIGHT) & (y >= c_BOTTOM) & (y <= c_TOP);
    if (!valid) return;
    int ix = (int)floorf(__fdiv_rn(x - c_LEFT,   c_HSTEP));
    int iy = (int)floorf(__fdiv_rn(y - c_BOTTOM, c_VSTEP));
    if (x == c_RIGHT) ix = NX - 1;
    if (y == c_TOP)   iy = NY - 1;
    ix = min(max(ix, 0), NX - 1);
    iy = min(max(iy, 0), NY - 1);
    int flat = (NY - 1 - iy) * NX + ix;
    atomicAdd(out + flat, 1.0f);  // no return use -> RED.E.ADD.F32
}

__global__ void __launch_bounds__(256)
hist_kernel(const float4* __restrict__ xs4, const float4* __restrict__ ys4,
            const float* __restrict__ mis, float* __restrict__ out) {
    int i = blockIdx.x * blockDim.x + threadIdx.x;  // one float4 per thread
    float mx = mis[0];
    float my = mis[1];
    float4 x4 = xs4[i];
    float4 y4 = ys4[i];
    deposit(x4.x - mx, y4.x - my, out);
    deposit(x4.y - mx, y4.y - my, out);
    deposit(x4.z - mx, y4.z - my, out);
    deposit(x4.w - mx, y4.w - my, out);
}

extern "C" void kernel_launch(void* const* d_in, const int* in_sizes, int n_in,
                              void* d_out, int out_size) {
    const float* xs  = (const float*)d_in[0];
    const float* ys  = (const float*)d_in[1];
    const float* mis = (const float*)d_in[2];
    float* out = (float*)d_out;

    // 1) zero the image (out_size = NX*NY floats, divisible by 4)
    int n4 = out_size / 4;
    zero_out_kernel<<<(n4 + 255) / 256, 256>>>((float4*)out, n4);

    // 2) histogram: 16,777,216 particles, 4 per thread
    int work = N_PARTICLES / 4;          // 4,194,304 threads
    hist_kernel<<<work / 256, 256>>>((const float4*)xs, (const float4*)ys, mis, out);
}